// round 2
// baseline (speedup 1.0000x reference)
#include <cuda_runtime.h>
#include <math.h>

#define Bb 2
#define Ll 384
#define Dd 128
#define NH 8
#define DHSc 16
#define NPC 12            // DHP*3
#define FEAT 1280

// ---------------- scratch (no allocations allowed) ----------------
static __device__ __align__(16) float g_qs[Bb*NH*Ll*DHSc];
static __device__ __align__(16) float g_ks[Bb*NH*Ll*DHSc];
static __device__ __align__(16) float g_vs[Bb*NH*Ll*DHSc];
static __device__ __align__(16) float g_qp[Bb*NH*Ll*NPC];
static __device__ __align__(16) float g_kp[Bb*NH*Ll*NPC];
static __device__ __align__(16) float g_vp[Bb*NH*Ll*NPC];
static __device__ __align__(16) float g_qq[Bb*NH*Ll];
static __device__ __align__(16) float g_kk[Bb*NH*Ll];
static __device__ __align__(16) float g_bias[Bb*NH*Ll*Ll];
static __device__ __align__(16) float g_feat[Bb*Ll*FEAT];

// ---------------- kernel 1: projections ----------------
__global__ __launch_bounds__(128) void proj_kernel(
    const float* __restrict__ x, const float* __restrict__ r, const float* __restrict__ t,
    const float* __restrict__ Wqs, const float* __restrict__ Wks, const float* __restrict__ Wvs,
    const float* __restrict__ Wqp, const float* __restrict__ Wkp, const float* __restrict__ Wvp)
{
    int bi = blockIdx.x;
    int b = bi / Ll, i = bi % Ll;
    int tid = threadIdx.x;
    __shared__ float xs[Dd];
    __shared__ float rs[9], ts[3];
    __shared__ float xp[96];
    __shared__ float sq[96];
    xs[tid] = x[bi * Dd + tid];
    if (tid < 9) rs[tid] = r[bi * 9 + tid];
    else if (tid >= 16 && tid < 19) ts[tid - 16] = t[bi * 3 + (tid - 16)];
    __syncthreads();
    {
        float a0 = 0.f, a1 = 0.f, a2 = 0.f;
        #pragma unroll 4
        for (int k = 0; k < Dd; k++) {
            float xv = xs[k];
            a0 += xv * Wqs[k * Dd + tid];
            a1 += xv * Wks[k * Dd + tid];
            a2 += xv * Wvs[k * Dd + tid];
        }
        int n = tid >> 4, d = tid & 15;
        int o = ((b * NH + n) * Ll + i) * DHSc + d;
        g_qs[o] = a0; g_ks[o] = a1; g_vs[o] = a2;
    }
    #pragma unroll
    for (int w = 0; w < 3; w++) {
        const float* W = (w == 0) ? Wqp : (w == 1) ? Wkp : Wvp;
        float* dst = (w == 0) ? g_qp : (w == 1) ? g_kp : g_vp;
        if (tid < 96) {
            float a = 0.f;
            #pragma unroll 4
            for (int k = 0; k < Dd; k++) a += xs[k] * W[k * 96 + tid];
            xp[tid] = a;
        }
        __syncthreads();
        if (tid < 96) {
            int n = tid / 12, pc = tid % 12, p = pc / 3, c = pc % 3;
            const float* xb = &xp[n * 12 + p * 3];
            // qp[n,p,c] = sum_k xp[k] * r[b,i,k,c] + t[b,i,c]
            float v = xb[0] * rs[c] + xb[1] * rs[3 + c] + xb[2] * rs[6 + c] + ts[c];
            dst[((b * NH + n) * Ll + i) * NPC + pc] = v;
            sq[tid] = v * v;
        }
        __syncthreads();
        if (w < 2 && tid < NH) {
            float s = 0.f;
            #pragma unroll
            for (int m = 0; m < 12; m++) s += sq[tid * 12 + m];
            (w == 0 ? g_qq : g_kk)[(b * NH + tid) * Ll + i] = s;
        }
        __syncthreads();
    }
}

// ---------------- kernel 2: bias_pair = e @ Wb ----------------
__global__ __launch_bounds__(256) void bias_kernel(
    const float* __restrict__ e, const float* __restrict__ Wb)
{
    int bi = blockIdx.x;
    int b = bi / Ll, i = bi % Ll;
    int tid = threadIdx.x;
    int warp = tid >> 5, lane = tid & 31;
    // each lane owns 4 d-values of Wb, kept in registers
    float wreg[4][NH];
    #pragma unroll
    for (int q = 0; q < 4; q++)
        #pragma unroll
        for (int n = 0; n < NH; n++)
            wreg[q][n] = Wb[(lane * 4 + q) * NH + n];
    const float4* erow = (const float4*)(e + (size_t)bi * Ll * Dd);
    for (int j = warp; j < Ll; j += 8) {
        float4 v = erow[j * 32 + lane];
        float acc[NH];
        #pragma unroll
        for (int n = 0; n < NH; n++)
            acc[n] = v.x * wreg[0][n] + v.y * wreg[1][n] + v.z * wreg[2][n] + v.w * wreg[3][n];
        #pragma unroll
        for (int n = 0; n < NH; n++)
            #pragma unroll
            for (int off = 16; off > 0; off >>= 1)
                acc[n] += __shfl_xor_sync(0xffffffffu, acc[n], off);
        if (lane == 0) {
            #pragma unroll
            for (int n = 0; n < NH; n++)
                g_bias[((b * NH + n) * Ll + i) * Ll + j] = acc[n];
        }
    }
}

// ---------------- kernel 3: logits + softmax + all attention outputs ----------------
__global__ __launch_bounds__(256) void attn_kernel(
    const float* __restrict__ e, const float* __restrict__ r, const float* __restrict__ t,
    const float* __restrict__ gamma)
{
    int bi = blockIdx.x;
    int b = bi / Ll, i = bi % Ll;
    int tid = threadIdx.x;
    int warp = tid >> 5, lane = tid & 31;

    __shared__ __align__(16) float smem_u[4096];    // attn rows (3072) then out_pair reduction (4096)
    __shared__ __align__(16) float attn_t[Ll * NH]; // attn transposed: [j][n]
    __shared__ float sqs[NH * DHSc];
    __shared__ float sqp[NH * NPC];
    __shared__ float sqq[NH], gam[NH];
    __shared__ float rs[9], ts[3];
    __shared__ float op_s[96], opl2[96];

    float* attn = smem_u;

    if (tid < 128) {
        int n = tid >> 4, d = tid & 15;
        sqs[tid] = g_qs[((b * NH + n) * Ll + i) * DHSc + d];
    } else if (tid < 224) {
        int m = tid - 128, n = m / 12, pc = m % 12;
        sqp[m] = g_qp[((b * NH + n) * Ll + i) * NPC + pc];
    } else if (tid < 232) {
        int n = tid - 224;
        sqq[n] = g_qq[(b * NH + n) * Ll + i];
        gam[n] = gamma[n];
    } else if (tid < 241) {
        rs[tid - 232] = r[bi * 9 + (tid - 232)];
    } else if (tid < 244) {
        ts[tid - 241] = t[bi * 3 + (tid - 241)];
    }
    __syncthreads();

    // ---- logits ----
    for (int m = tid; m < NH * Ll; m += 256) {
        int n = m / Ll, j = m - n * Ll;
        const float4* kr = (const float4*)&g_ks[((b * NH + n) * Ll + j) * DHSc];
        float4 k0 = kr[0], k1 = kr[1], k2 = kr[2], k3 = kr[3];
        const float* q = &sqs[n * DHSc];
        float s = q[0]*k0.x + q[1]*k0.y + q[2]*k0.z + q[3]*k0.w
                + q[4]*k1.x + q[5]*k1.y + q[6]*k1.z + q[7]*k1.w
                + q[8]*k2.x + q[9]*k2.y + q[10]*k2.z + q[11]*k2.w
                + q[12]*k3.x + q[13]*k3.y + q[14]*k3.z + q[15]*k3.w;
        const float* kp = &g_kp[((b * NH + n) * Ll + j) * NPC];
        const float* qp = &sqp[n * NPC];
        float cr = 0.f;
        #pragma unroll
        for (int u = 0; u < NPC; u++) cr += qp[u] * kp[u];
        float d2 = sqq[n] + g_kk[(b * NH + n) * Ll + j] - 2.f * cr;
        float lg = 0.5773502691896258f *
            (0.25f * s + g_bias[((b * NH + n) * Ll + i) * Ll + j] - 0.125f * gam[n] * d2);
        attn[m] = lg;
    }
    __syncthreads();

    // ---- softmax: warp w handles head w ----
    {
        float* row = &attn[warp * Ll];
        float mx = -1e30f;
        for (int j = lane; j < Ll; j += 32) mx = fmaxf(mx, row[j]);
        #pragma unroll
        for (int off = 16; off > 0; off >>= 1)
            mx = fmaxf(mx, __shfl_xor_sync(0xffffffffu, mx, off));
        float sum = 0.f;
        for (int j = lane; j < Ll; j += 32) {
            float ex = __expf(row[j] - mx);
            row[j] = ex;
            sum += ex;
        }
        #pragma unroll
        for (int off = 16; off > 0; off >>= 1)
            sum += __shfl_xor_sync(0xffffffffu, sum, off);
        float inv = 1.f / sum;
        for (int j = lane; j < Ll; j += 32) {
            float a = row[j] * inv;
            row[j] = a;
            attn_t[j * NH + warp] = a;
        }
    }
    __syncthreads();

    float* feat = &g_feat[bi * FEAT];

    // ---- out_scalar (attn @ vs) and op (attn @ vp) ----
    if (tid < 128) {
        int n = tid >> 4, d = tid & 15;
        const float* row = &attn[n * Ll];
        const float* vb = &g_vs[((b * NH + n) * Ll) * DHSc + d];
        float acc = 0.f;
        for (int j = 0; j < Ll; j++) acc += row[j] * vb[j * DHSc];
        feat[tid] = acc;                                  // out_scalar: n*16+d
    } else if (tid < 224) {
        int m = tid - 128, n = m / 12, pc = m % 12;
        const float* row = &attn[n * Ll];
        const float* vb = &g_vp[((b * NH + n) * Ll) * NPC + pc];
        float acc = 0.f;
        for (int j = 0; j < Ll; j++) acc += row[j] * vb[j * NPC];
        op_s[m] = acc;
    }
    __syncthreads();

    // ---- op_local (inverse rotation) + norm ----
    if (tid < 96) {
        int pc = tid % 12, nb = tid - pc;
        int p3 = (pc / 3) * 3, c = pc % 3;
        const float* ob = &op_s[nb + p3];
        // op_local[n,p,c] = sum_k (op[n,p,k] - t[k]) * r[b,i,c,k]
        float v = (ob[0] - ts[0]) * rs[c * 3 + 0]
                + (ob[1] - ts[1]) * rs[c * 3 + 1]
                + (ob[2] - ts[2]) * rs[c * 3 + 2];
        feat[1152 + tid] = v;                             // out_point: n*12+p*3+c
        opl2[tid] = v * v;
    }
    __syncthreads();
    if (tid < 32) {
        int base = (tid >> 2) * 12 + (tid & 3) * 3;
        feat[1248 + tid] = sqrtf(opl2[base] + opl2[base + 1] + opl2[base + 2]); // out_norm: n*4+p
    }

    // ---- out_pair = attn @ e  (the big HBM read) ----
    {
        const float4* ebase = (const float4*)(e + (size_t)bi * Ll * Dd);
        float acc[NH][4];
        #pragma unroll
        for (int n = 0; n < NH; n++) { acc[n][0]=0.f; acc[n][1]=0.f; acc[n][2]=0.f; acc[n][3]=0.f; }
        int j0 = warp * 48;
        #pragma unroll 2
        for (int j = j0; j < j0 + 48; j++) {
            float4 ev = ebase[j * 32 + lane];
            float4 a0 = *(const float4*)&attn_t[j * NH];
            float4 a1 = *(const float4*)&attn_t[j * NH + 4];
            float an[NH] = {a0.x, a0.y, a0.z, a0.w, a1.x, a1.y, a1.z, a1.w};
            #pragma unroll
            for (int n = 0; n < NH; n++) {
                acc[n][0] += an[n] * ev.x;
                acc[n][1] += an[n] * ev.y;
                acc[n][2] += an[n] * ev.z;
                acc[n][3] += an[n] * ev.w;
            }
        }
        __syncthreads();   // attn-row region free now; reuse smem_u for reduction
        #pragma unroll
        for (int stride = 4; stride >= 1; stride >>= 1) {
            if (warp >= stride && warp < 2 * stride) {
                float* dstb = &smem_u[(warp - stride) * 1024];
                #pragma unroll
                for (int n = 0; n < NH; n++)
                    *(float4*)&dstb[n * 128 + lane * 4] =
                        make_float4(acc[n][0], acc[n][1], acc[n][2], acc[n][3]);
            }
            __syncthreads();
            if (warp < stride) {
                const float* srcb = &smem_u[warp * 1024];
                #pragma unroll
                for (int n = 0; n < NH; n++) {
                    float4 v = *(const float4*)&srcb[n * 128 + lane * 4];
                    acc[n][0] += v.x; acc[n][1] += v.y; acc[n][2] += v.z; acc[n][3] += v.w;
                }
            }
            __syncthreads();
        }
        if (warp == 0) {
            #pragma unroll
            for (int n = 0; n < NH; n++)
                *(float4*)&feat[128 + n * 128 + lane * 4] =
                    make_float4(acc[n][0], acc[n][1], acc[n][2], acc[n][3]); // out_pair: 128+n*128+d
        }
    }
}

// ---------------- kernel 4: out = feat @ Wo + bo ----------------
#define TMR 8
#define KC 64
__global__ __launch_bounds__(256) void out_kernel(
    const float* __restrict__ Wo, const float* __restrict__ bo, float* __restrict__ out)
{
    int row0 = blockIdx.x * TMR;
    int tid = threadIdx.x;
    int tx = tid & 31;     // cols tx*4 .. tx*4+3
    int ty = tid >> 5;     // row within tile
    __shared__ __align__(16) float As[TMR * KC];
    __shared__ __align__(16) float Bs[KC * Dd];
    float acc0 = 0.f, acc1 = 0.f, acc2 = 0.f, acc3 = 0.f;
    for (int k0 = 0; k0 < FEAT; k0 += KC) {
        for (int m = tid; m < TMR * KC; m += 256) {
            int rr = m >> 6, kk = m & (KC - 1);
            As[m] = g_feat[(row0 + rr) * FEAT + k0 + kk];
        }
        {
            const float4* wsrc = (const float4*)(Wo + (size_t)k0 * Dd);
            float4* bdst = (float4*)Bs;
            for (int m = tid; m < KC * Dd / 4; m += 256) bdst[m] = wsrc[m];
        }
        __syncthreads();
        #pragma unroll 4
        for (int kk = 0; kk < KC; kk++) {
            float av = As[ty * KC + kk];
            float4 bv = *(const float4*)&Bs[kk * Dd + tx * 4];
            acc0 += av * bv.x; acc1 += av * bv.y; acc2 += av * bv.z; acc3 += av * bv.w;
        }
        __syncthreads();
    }
    float4 bb = *(const float4*)&bo[tx * 4];
    int row = row0 + ty;
    *(float4*)&out[(size_t)row * Dd + tx * 4] =
        make_float4(acc0 + bb.x, acc1 + bb.y, acc2 + bb.z, acc3 + bb.w);
}

// ---------------- launch ----------------
extern "C" void kernel_launch(void* const* d_in, const int* in_sizes, int n_in,
                              void* d_out, int out_size) {
    const float* x     = (const float*)d_in[0];
    const float* e     = (const float*)d_in[1];
    const float* r     = (const float*)d_in[2];
    const float* t     = (const float*)d_in[3];
    const float* Wqs   = (const float*)d_in[4];
    const float* Wks   = (const float*)d_in[5];
    const float* Wvs   = (const float*)d_in[6];
    const float* Wb    = (const float*)d_in[7];
    const float* Wqp   = (const float*)d_in[8];
    const float* Wkp   = (const float*)d_in[9];
    const float* Wvp   = (const float*)d_in[10];
    const float* gamma = (const float*)d_in[11];
    const float* Wo    = (const float*)d_in[12];
    const float* bo    = (const float*)d_in[13];
    float* out = (float*)d_out;

    proj_kernel<<<Bb * Ll, 128>>>(x, r, t, Wqs, Wks, Wvs, Wqp, Wkp, Wvp);
    bias_kernel<<<Bb * Ll, 256>>>(e, Wb);
    attn_kernel<<<Bb * Ll, 256>>>(e, r, t, gamma);
    out_kernel<<<(Bb * Ll) / TMR, 256>>>(Wo, bo, out);
}

// round 3
// speedup vs baseline: 1.0014x; 1.0014x over previous
#include <cuda_runtime.h>
#include <math.h>

#define Bb 2
#define Ll 384
#define Dd 128
#define NH 8
#define DHSc 16
#define NPC 12            // DHP*3
#define FEAT 1280

// ---------------- scratch (no allocations allowed) ----------------
static __device__ __align__(16) float g_qs[Bb*NH*Ll*DHSc];
static __device__ __align__(16) float g_ks[Bb*NH*Ll*DHSc];
static __device__ __align__(16) float g_vs[Bb*NH*Ll*DHSc];
static __device__ __align__(16) float g_qp[Bb*NH*Ll*NPC];
static __device__ __align__(16) float g_kp[Bb*NH*Ll*NPC];
static __device__ __align__(16) float g_vp[Bb*NH*Ll*NPC];
static __device__ __align__(16) float g_qq[Bb*NH*Ll];
static __device__ __align__(16) float g_kk[Bb*NH*Ll];
static __device__ __align__(16) float g_bias[Bb*NH*Ll*Ll];
static __device__ __align__(16) float g_feat[Bb*Ll*FEAT];

// ---------------- kernel 1: projections ----------------
__global__ __launch_bounds__(128) void proj_kernel(
    const float* __restrict__ x, const float* __restrict__ r, const float* __restrict__ t,
    const float* __restrict__ Wqs, const float* __restrict__ Wks, const float* __restrict__ Wvs,
    const float* __restrict__ Wqp, const float* __restrict__ Wkp, const float* __restrict__ Wvp)
{
    int bi = blockIdx.x;
    int b = bi / Ll, i = bi % Ll;
    int tid = threadIdx.x;
    __shared__ float xs[Dd];
    __shared__ float rs[9], ts[3];
    __shared__ float xp[96];
    __shared__ float sq[96];
    xs[tid] = x[bi * Dd + tid];
    if (tid < 9) rs[tid] = r[bi * 9 + tid];
    else if (tid >= 16 && tid < 19) ts[tid - 16] = t[bi * 3 + (tid - 16)];
    __syncthreads();
    {
        float a0 = 0.f, a1 = 0.f, a2 = 0.f;
        #pragma unroll 4
        for (int k = 0; k < Dd; k++) {
            float xv = xs[k];
            a0 += xv * Wqs[k * Dd + tid];
            a1 += xv * Wks[k * Dd + tid];
            a2 += xv * Wvs[k * Dd + tid];
        }
        int n = tid >> 4, d = tid & 15;
        int o = ((b * NH + n) * Ll + i) * DHSc + d;
        g_qs[o] = a0; g_ks[o] = a1; g_vs[o] = a2;
    }
    #pragma unroll
    for (int w = 0; w < 3; w++) {
        const float* W = (w == 0) ? Wqp : (w == 1) ? Wkp : Wvp;
        float* dst = (w == 0) ? g_qp : (w == 1) ? g_kp : g_vp;
        if (tid < 96) {
            float a = 0.f;
            #pragma unroll 4
            for (int k = 0; k < Dd; k++) a += xs[k] * W[k * 96 + tid];
            xp[tid] = a;
        }
        __syncthreads();
        if (tid < 96) {
            int n = tid / 12, pc = tid % 12, p = pc / 3, c = pc % 3;
            const float* xb = &xp[n * 12 + p * 3];
            // qp[n,p,c] = sum_k xp[k] * r[b,i,k,c] + t[b,i,c]
            float v = xb[0] * rs[c] + xb[1] * rs[3 + c] + xb[2] * rs[6 + c] + ts[c];
            dst[((b * NH + n) * Ll + i) * NPC + pc] = v;
            sq[tid] = v * v;
        }
        __syncthreads();
        if (w < 2 && tid < NH) {
            float s = 0.f;
            #pragma unroll
            for (int m = 0; m < 12; m++) s += sq[tid * 12 + m];
            (w == 0 ? g_qq : g_kk)[(b * NH + tid) * Ll + i] = s;
        }
        __syncthreads();
    }
}

// ---------------- kernel 2: bias_pair = e @ Wb ----------------
__global__ __launch_bounds__(256) void bias_kernel(
    const float* __restrict__ e, const float* __restrict__ Wb)
{
    int bi = blockIdx.x;
    int b = bi / Ll, i = bi % Ll;
    int tid = threadIdx.x;
    int warp = tid >> 5, lane = tid & 31;
    // each lane owns 4 d-values of Wb, kept in registers
    float wreg[4][NH];
    #pragma unroll
    for (int q = 0; q < 4; q++)
        #pragma unroll
        for (int n = 0; n < NH; n++)
            wreg[q][n] = Wb[(lane * 4 + q) * NH + n];
    const float4* erow = (const float4*)(e + (size_t)bi * Ll * Dd);
    for (int j = warp; j < Ll; j += 8) {
        float4 v = erow[j * 32 + lane];
        float acc[NH];
        #pragma unroll
        for (int n = 0; n < NH; n++)
            acc[n] = v.x * wreg[0][n] + v.y * wreg[1][n] + v.z * wreg[2][n] + v.w * wreg[3][n];
        #pragma unroll
        for (int n = 0; n < NH; n++)
            #pragma unroll
            for (int off = 16; off > 0; off >>= 1)
                acc[n] += __shfl_xor_sync(0xffffffffu, acc[n], off);
        if (lane == 0) {
            #pragma unroll
            for (int n = 0; n < NH; n++)
                g_bias[((b * NH + n) * Ll + i) * Ll + j] = acc[n];
        }
    }
}

// ---------------- kernel 3: logits + softmax + all attention outputs ----------------
__global__ __launch_bounds__(256) void attn_kernel(
    const float* __restrict__ e, const float* __restrict__ r, const float* __restrict__ t,
    const float* __restrict__ gamma)
{
    int bi = blockIdx.x;
    int b = bi / Ll, i = bi % Ll;
    int tid = threadIdx.x;
    int warp = tid >> 5, lane = tid & 31;

    __shared__ __align__(16) float smem_u[4096];    // attn rows (3072) then out_pair reduction (4096)
    __shared__ __align__(16) float attn_t[Ll * NH]; // attn transposed: [j][n]
    __shared__ float sqs[NH * DHSc];
    __shared__ float sqp[NH * NPC];
    __shared__ float sqq[NH], gam[NH];
    __shared__ float rs[9], ts[3];
    __shared__ float op_s[96], opl2[96];

    float* attn = smem_u;

    if (tid < 128) {
        int n = tid >> 4, d = tid & 15;
        sqs[tid] = g_qs[((b * NH + n) * Ll + i) * DHSc + d];
    } else if (tid < 224) {
        int m = tid - 128, n = m / 12, pc = m % 12;
        sqp[m] = g_qp[((b * NH + n) * Ll + i) * NPC + pc];
    } else if (tid < 232) {
        int n = tid - 224;
        sqq[n] = g_qq[(b * NH + n) * Ll + i];
        gam[n] = gamma[n];
    } else if (tid < 241) {
        rs[tid - 232] = r[bi * 9 + (tid - 232)];
    } else if (tid < 244) {
        ts[tid - 241] = t[bi * 3 + (tid - 241)];
    }
    __syncthreads();

    // ---- logits ----
    for (int m = tid; m < NH * Ll; m += 256) {
        int n = m / Ll, j = m - n * Ll;
        const float4* kr = (const float4*)&g_ks[((b * NH + n) * Ll + j) * DHSc];
        float4 k0 = kr[0], k1 = kr[1], k2 = kr[2], k3 = kr[3];
        const float* q = &sqs[n * DHSc];
        float s = q[0]*k0.x + q[1]*k0.y + q[2]*k0.z + q[3]*k0.w
                + q[4]*k1.x + q[5]*k1.y + q[6]*k1.z + q[7]*k1.w
                + q[8]*k2.x + q[9]*k2.y + q[10]*k2.z + q[11]*k2.w
                + q[12]*k3.x + q[13]*k3.y + q[14]*k3.z + q[15]*k3.w;
        const float* kp = &g_kp[((b * NH + n) * Ll + j) * NPC];
        const float* qp = &sqp[n * NPC];
        float cr = 0.f;
        #pragma unroll
        for (int u = 0; u < NPC; u++) cr += qp[u] * kp[u];
        float d2 = sqq[n] + g_kk[(b * NH + n) * Ll + j] - 2.f * cr;
        float lg = 0.5773502691896258f *
            (0.25f * s + g_bias[((b * NH + n) * Ll + i) * Ll + j] - 0.125f * gam[n] * d2);
        attn[m] = lg;
    }
    __syncthreads();

    // ---- softmax: warp w handles head w ----
    {
        float* row = &attn[warp * Ll];
        float mx = -1e30f;
        for (int j = lane; j < Ll; j += 32) mx = fmaxf(mx, row[j]);
        #pragma unroll
        for (int off = 16; off > 0; off >>= 1)
            mx = fmaxf(mx, __shfl_xor_sync(0xffffffffu, mx, off));
        float sum = 0.f;
        for (int j = lane; j < Ll; j += 32) {
            float ex = __expf(row[j] - mx);
            row[j] = ex;
            sum += ex;
        }
        #pragma unroll
        for (int off = 16; off > 0; off >>= 1)
            sum += __shfl_xor_sync(0xffffffffu, sum, off);
        float inv = 1.f / sum;
        for (int j = lane; j < Ll; j += 32) {
            float a = row[j] * inv;
            row[j] = a;
            attn_t[j * NH + warp] = a;
        }
    }
    __syncthreads();

    float* feat = &g_feat[bi * FEAT];

    // ---- out_scalar (attn @ vs) and op (attn @ vp) ----
    if (tid < 128) {
        int n = tid >> 4, d = tid & 15;
        const float* row = &attn[n * Ll];
        const float* vb = &g_vs[((b * NH + n) * Ll) * DHSc + d];
        float acc = 0.f;
        for (int j = 0; j < Ll; j++) acc += row[j] * vb[j * DHSc];
        feat[tid] = acc;                                  // out_scalar: n*16+d
    } else if (tid < 224) {
        int m = tid - 128, n = m / 12, pc = m % 12;
        const float* row = &attn[n * Ll];
        const float* vb = &g_vp[((b * NH + n) * Ll) * NPC + pc];
        float acc = 0.f;
        for (int j = 0; j < Ll; j++) acc += row[j] * vb[j * NPC];
        op_s[m] = acc;
    }
    __syncthreads();

    // ---- op_local (inverse rotation) + norm ----
    if (tid < 96) {
        int pc = tid % 12, nb = tid - pc;
        int p3 = (pc / 3) * 3, c = pc % 3;
        const float* ob = &op_s[nb + p3];
        // op_local[n,p,c] = sum_k (op[n,p,k] - t[k]) * r[b,i,c,k]
        float v = (ob[0] - ts[0]) * rs[c * 3 + 0]
                + (ob[1] - ts[1]) * rs[c * 3 + 1]
                + (ob[2] - ts[2]) * rs[c * 3 + 2];
        feat[1152 + tid] = v;                             // out_point: n*12+p*3+c
        opl2[tid] = v * v;
    }
    __syncthreads();
    if (tid < 32) {
        int base = (tid >> 2) * 12 + (tid & 3) * 3;
        feat[1248 + tid] = sqrtf(opl2[base] + opl2[base + 1] + opl2[base + 2]); // out_norm: n*4+p
    }

    // ---- out_pair = attn @ e  (the big HBM read) ----
    {
        const float4* ebase = (const float4*)(e + (size_t)bi * Ll * Dd);
        float acc[NH][4];
        #pragma unroll
        for (int n = 0; n < NH; n++) { acc[n][0]=0.f; acc[n][1]=0.f; acc[n][2]=0.f; acc[n][3]=0.f; }
        int j0 = warp * 48;
        #pragma unroll 2
        for (int j = j0; j < j0 + 48; j++) {
            float4 ev = ebase[j * 32 + lane];
            float4 a0 = *(const float4*)&attn_t[j * NH];
            float4 a1 = *(const float4*)&attn_t[j * NH + 4];
            float an[NH] = {a0.x, a0.y, a0.z, a0.w, a1.x, a1.y, a1.z, a1.w};
            #pragma unroll
            for (int n = 0; n < NH; n++) {
                acc[n][0] += an[n] * ev.x;
                acc[n][1] += an[n] * ev.y;
                acc[n][2] += an[n] * ev.z;
                acc[n][3] += an[n] * ev.w;
            }
        }
        __syncthreads();   // attn-row region free now; reuse smem_u for reduction
        #pragma unroll
        for (int stride = 4; stride >= 1; stride >>= 1) {
            if (warp >= stride && warp < 2 * stride) {
                float* dstb = &smem_u[(warp - stride) * 1024];
                #pragma unroll
                for (int n = 0; n < NH; n++)
                    *(float4*)&dstb[n * 128 + lane * 4] =
                        make_float4(acc[n][0], acc[n][1], acc[n][2], acc[n][3]);
            }
            __syncthreads();
            if (warp < stride) {
                const float* srcb = &smem_u[warp * 1024];
                #pragma unroll
                for (int n = 0; n < NH; n++) {
                    float4 v = *(const float4*)&srcb[n * 128 + lane * 4];
                    acc[n][0] += v.x; acc[n][1] += v.y; acc[n][2] += v.z; acc[n][3] += v.w;
                }
            }
            __syncthreads();
        }
        if (warp == 0) {
            #pragma unroll
            for (int n = 0; n < NH; n++)
                *(float4*)&feat[128 + n * 128 + lane * 4] =
                    make_float4(acc[n][0], acc[n][1], acc[n][2], acc[n][3]); // out_pair: 128+n*128+d
        }
    }
}

// ---------------- kernel 4: out = feat @ Wo + bo ----------------
#define TMR 8
#define KC 64
__global__ __launch_bounds__(256) void out_kernel(
    const float* __restrict__ Wo, const float* __restrict__ bo, float* __restrict__ out)
{
    int row0 = blockIdx.x * TMR;
    int tid = threadIdx.x;
    int tx = tid & 31;     // cols tx*4 .. tx*4+3
    int ty = tid >> 5;     // row within tile
    __shared__ __align__(16) float As[TMR * KC];
    __shared__ __align__(16) float Bs[KC * Dd];
    float acc0 = 0.f, acc1 = 0.f, acc2 = 0.f, acc3 = 0.f;
    for (int k0 = 0; k0 < FEAT; k0 += KC) {
        for (int m = tid; m < TMR * KC; m += 256) {
            int rr = m >> 6, kk = m & (KC - 1);
            As[m] = g_feat[(row0 + rr) * FEAT + k0 + kk];
        }
        {
            const float4* wsrc = (const float4*)(Wo + (size_t)k0 * Dd);
            float4* bdst = (float4*)Bs;
            for (int m = tid; m < KC * Dd / 4; m += 256) bdst[m] = wsrc[m];
        }
        __syncthreads();
        #pragma unroll 4
        for (int kk = 0; kk < KC; kk++) {
            float av = As[ty * KC + kk];
            float4 bv = *(const float4*)&Bs[kk * Dd + tx * 4];
            acc0 += av * bv.x; acc1 += av * bv.y; acc2 += av * bv.z; acc3 += av * bv.w;
        }
        __syncthreads();
    }
    float4 bb = *(const float4*)&bo[tx * 4];
    int row = row0 + ty;
    *(float4*)&out[(size_t)row * Dd + tx * 4] =
        make_float4(acc0 + bb.x, acc1 + bb.y, acc2 + bb.z, acc3 + bb.w);
}

// ---------------- launch ----------------
extern "C" void kernel_launch(void* const* d_in, const int* in_sizes, int n_in,
                              void* d_out, int out_size) {
    const float* x     = (const float*)d_in[0];
    const float* e     = (const float*)d_in[1];
    const float* r     = (const float*)d_in[2];
    const float* t     = (const float*)d_in[3];
    const float* Wqs   = (const float*)d_in[4];
    const float* Wks   = (const float*)d_in[5];
    const float* Wvs   = (const float*)d_in[6];
    const float* Wb    = (const float*)d_in[7];
    const float* Wqp   = (const float*)d_in[8];
    const float* Wkp   = (const float*)d_in[9];
    const float* Wvp   = (const float*)d_in[10];
    const float* gamma = (const float*)d_in[11];
    const float* Wo    = (const float*)d_in[12];
    const float* bo    = (const float*)d_in[13];
    float* out = (float*)d_out;

    proj_kernel<<<Bb * Ll, 128>>>(x, r, t, Wqs, Wks, Wvs, Wqp, Wkp, Wvp);
    bias_kernel<<<Bb * Ll, 256>>>(e, Wb);
    attn_kernel<<<Bb * Ll, 256>>>(e, r, t, gamma);
    out_kernel<<<(Bb * Ll) / TMR, 256>>>(Wo, bo, out);
}

// round 4
// speedup vs baseline: 1.0053x; 1.0039x over previous
#include <cuda_runtime.h>
#include <math.h>

#define Bb 2
#define Ll 384
#define Dd 128
#define NH 8
#define DHSc 16
#define NPC 12            // DHP*3
#define FEAT 1280

// ---------------- scratch (no allocations allowed) ----------------
static __device__ __align__(16) float g_qs[Bb*NH*Ll*DHSc];
static __device__ __align__(16) float g_ks[Bb*NH*Ll*DHSc];
static __device__ __align__(16) float g_vs[Bb*NH*Ll*DHSc];
static __device__ __align__(16) float g_qp[Bb*NH*Ll*NPC];
static __device__ __align__(16) float g_kp[Bb*NH*Ll*NPC];
static __device__ __align__(16) float g_vp[Bb*NH*Ll*NPC];
static __device__ __align__(16) float g_qq[Bb*NH*Ll];
static __device__ __align__(16) float g_kk[Bb*NH*Ll];
static __device__ __align__(16) float g_bias[Bb*NH*Ll*Ll];
static __device__ __align__(16) float g_feat[Bb*Ll*FEAT];

// ---------------- kernel 1: projections ----------------
__global__ __launch_bounds__(128) void proj_kernel(
    const float* __restrict__ x, const float* __restrict__ r, const float* __restrict__ t,
    const float* __restrict__ Wqs, const float* __restrict__ Wks, const float* __restrict__ Wvs,
    const float* __restrict__ Wqp, const float* __restrict__ Wkp, const float* __restrict__ Wvp)
{
    int bi = blockIdx.x;
    int b = bi / Ll, i = bi % Ll;
    int tid = threadIdx.x;
    __shared__ float xs[Dd];
    __shared__ float rs[9], ts[3];
    __shared__ float xp[96];
    __shared__ float sq[96];
    xs[tid] = x[bi * Dd + tid];
    if (tid < 9) rs[tid] = r[bi * 9 + tid];
    else if (tid >= 16 && tid < 19) ts[tid - 16] = t[bi * 3 + (tid - 16)];
    __syncthreads();
    {
        float a0 = 0.f, a1 = 0.f, a2 = 0.f;
        #pragma unroll 4
        for (int k = 0; k < Dd; k++) {
            float xv = xs[k];
            a0 += xv * Wqs[k * Dd + tid];
            a1 += xv * Wks[k * Dd + tid];
            a2 += xv * Wvs[k * Dd + tid];
        }
        int n = tid >> 4, d = tid & 15;
        int o = ((b * NH + n) * Ll + i) * DHSc + d;
        g_qs[o] = a0; g_ks[o] = a1; g_vs[o] = a2;
    }
    #pragma unroll
    for (int w = 0; w < 3; w++) {
        const float* W = (w == 0) ? Wqp : (w == 1) ? Wkp : Wvp;
        float* dst = (w == 0) ? g_qp : (w == 1) ? g_kp : g_vp;
        if (tid < 96) {
            float a = 0.f;
            #pragma unroll 4
            for (int k = 0; k < Dd; k++) a += xs[k] * W[k * 96 + tid];
            xp[tid] = a;
        }
        __syncthreads();
        if (tid < 96) {
            int n = tid / 12, pc = tid % 12, p = pc / 3, c = pc % 3;
            const float* xb = &xp[n * 12 + p * 3];
            // qp[n,p,c] = sum_k xp[k] * r[b,i,k,c] + t[b,i,c]
            float v = xb[0] * rs[c] + xb[1] * rs[3 + c] + xb[2] * rs[6 + c] + ts[c];
            dst[((b * NH + n) * Ll + i) * NPC + pc] = v;
            sq[tid] = v * v;
        }
        __syncthreads();
        if (w < 2 && tid < NH) {
            float s = 0.f;
            #pragma unroll
            for (int m = 0; m < 12; m++) s += sq[tid * 12 + m];
            (w == 0 ? g_qq : g_kk)[(b * NH + tid) * Ll + i] = s;
        }
        __syncthreads();
    }
}

// ---------------- kernel 2: bias_pair = e @ Wb ----------------
__global__ __launch_bounds__(256) void bias_kernel(
    const float* __restrict__ e, const float* __restrict__ Wb)
{
    int bi = blockIdx.x;
    int b = bi / Ll, i = bi % Ll;
    int tid = threadIdx.x;
    int warp = tid >> 5, lane = tid & 31;
    // each lane owns 4 d-values of Wb, kept in registers
    float wreg[4][NH];
    #pragma unroll
    for (int q = 0; q < 4; q++)
        #pragma unroll
        for (int n = 0; n < NH; n++)
            wreg[q][n] = Wb[(lane * 4 + q) * NH + n];
    const float4* erow = (const float4*)(e + (size_t)bi * Ll * Dd);
    for (int j = warp; j < Ll; j += 8) {
        float4 v = erow[j * 32 + lane];
        float acc[NH];
        #pragma unroll
        for (int n = 0; n < NH; n++)
            acc[n] = v.x * wreg[0][n] + v.y * wreg[1][n] + v.z * wreg[2][n] + v.w * wreg[3][n];
        #pragma unroll
        for (int n = 0; n < NH; n++)
            #pragma unroll
            for (int off = 16; off > 0; off >>= 1)
                acc[n] += __shfl_xor_sync(0xffffffffu, acc[n], off);
        if (lane == 0) {
            #pragma unroll
            for (int n = 0; n < NH; n++)
                g_bias[((b * NH + n) * Ll + i) * Ll + j] = acc[n];
        }
    }
}

// ---------------- kernel 3: logits + softmax + all attention outputs ----------------
__global__ __launch_bounds__(256) void attn_kernel(
    const float* __restrict__ e, const float* __restrict__ r, const float* __restrict__ t,
    const float* __restrict__ gamma)
{
    int bi = blockIdx.x;
    int b = bi / Ll, i = bi % Ll;
    int tid = threadIdx.x;
    int warp = tid >> 5, lane = tid & 31;

    __shared__ __align__(16) float smem_u[4096];    // attn rows (3072) then out_pair reduction (4096)
    __shared__ __align__(16) float attn_t[Ll * NH]; // attn transposed: [j][n]
    __shared__ float sqs[NH * DHSc];
    __shared__ float sqp[NH * NPC];
    __shared__ float sqq[NH], gam[NH];
    __shared__ float rs[9], ts[3];
    __shared__ float op_s[96], opl2[96];

    float* attn = smem_u;

    if (tid < 128) {
        int n = tid >> 4, d = tid & 15;
        sqs[tid] = g_qs[((b * NH + n) * Ll + i) * DHSc + d];
    } else if (tid < 224) {
        int m = tid - 128, n = m / 12, pc = m % 12;
        sqp[m] = g_qp[((b * NH + n) * Ll + i) * NPC + pc];
    } else if (tid < 232) {
        int n = tid - 224;
        sqq[n] = g_qq[(b * NH + n) * Ll + i];
        gam[n] = gamma[n];
    } else if (tid < 241) {
        rs[tid - 232] = r[bi * 9 + (tid - 232)];
    } else if (tid < 244) {
        ts[tid - 241] = t[bi * 3 + (tid - 241)];
    }
    __syncthreads();

    // ---- logits ----
    for (int m = tid; m < NH * Ll; m += 256) {
        int n = m / Ll, j = m - n * Ll;
        const float4* kr = (const float4*)&g_ks[((b * NH + n) * Ll + j) * DHSc];
        float4 k0 = kr[0], k1 = kr[1], k2 = kr[2], k3 = kr[3];
        const float* q = &sqs[n * DHSc];
        float s = q[0]*k0.x + q[1]*k0.y + q[2]*k0.z + q[3]*k0.w
                + q[4]*k1.x + q[5]*k1.y + q[6]*k1.z + q[7]*k1.w
                + q[8]*k2.x + q[9]*k2.y + q[10]*k2.z + q[11]*k2.w
                + q[12]*k3.x + q[13]*k3.y + q[14]*k3.z + q[15]*k3.w;
        const float* kp = &g_kp[((b * NH + n) * Ll + j) * NPC];
        const float* qp = &sqp[n * NPC];
        float cr = 0.f;
        #pragma unroll
        for (int u = 0; u < NPC; u++) cr += qp[u] * kp[u];
        float d2 = sqq[n] + g_kk[(b * NH + n) * Ll + j] - 2.f * cr;
        float lg = 0.5773502691896258f *
            (0.25f * s + g_bias[((b * NH + n) * Ll + i) * Ll + j] - 0.125f * gam[n] * d2);
        attn[m] = lg;
    }
    __syncthreads();

    // ---- softmax: warp w handles head w ----
    {
        float* row = &attn[warp * Ll];
        float mx = -1e30f;
        for (int j = lane; j < Ll; j += 32) mx = fmaxf(mx, row[j]);
        #pragma unroll
        for (int off = 16; off > 0; off >>= 1)
            mx = fmaxf(mx, __shfl_xor_sync(0xffffffffu, mx, off));
        float sum = 0.f;
        for (int j = lane; j < Ll; j += 32) {
            float ex = __expf(row[j] - mx);
            row[j] = ex;
            sum += ex;
        }
        #pragma unroll
        for (int off = 16; off > 0; off >>= 1)
            sum += __shfl_xor_sync(0xffffffffu, sum, off);
        float inv = 1.f / sum;
        for (int j = lane; j < Ll; j += 32) {
            float a = row[j] * inv;
            row[j] = a;
            attn_t[j * NH + warp] = a;
        }
    }
    __syncthreads();

    float* feat = &g_feat[bi * FEAT];

    // ---- out_scalar (attn @ vs) and op (attn @ vp) ----
    if (tid < 128) {
        int n = tid >> 4, d = tid & 15;
        const float* row = &attn[n * Ll];
        const float* vb = &g_vs[((b * NH + n) * Ll) * DHSc + d];
        float acc = 0.f;
        for (int j = 0; j < Ll; j++) acc += row[j] * vb[j * DHSc];
        feat[tid] = acc;                                  // out_scalar: n*16+d
    } else if (tid < 224) {
        int m = tid - 128, n = m / 12, pc = m % 12;
        const float* row = &attn[n * Ll];
        const float* vb = &g_vp[((b * NH + n) * Ll) * NPC + pc];
        float acc = 0.f;
        for (int j = 0; j < Ll; j++) acc += row[j] * vb[j * NPC];
        op_s[m] = acc;
    }
    __syncthreads();

    // ---- op_local (inverse rotation) + norm ----
    if (tid < 96) {
        int pc = tid % 12, nb = tid - pc;
        int p3 = (pc / 3) * 3, c = pc % 3;
        const float* ob = &op_s[nb + p3];
        // op_local[n,p,c] = sum_k (op[n,p,k] - t[k]) * r[b,i,c,k]
        float v = (ob[0] - ts[0]) * rs[c * 3 + 0]
                + (ob[1] - ts[1]) * rs[c * 3 + 1]
                + (ob[2] - ts[2]) * rs[c * 3 + 2];
        feat[1152 + tid] = v;                             // out_point: n*12+p*3+c
        opl2[tid] = v * v;
    }
    __syncthreads();
    if (tid < 32) {
        int base = (tid >> 2) * 12 + (tid & 3) * 3;
        feat[1248 + tid] = sqrtf(opl2[base] + opl2[base + 1] + opl2[base + 2]); // out_norm: n*4+p
    }

    // ---- out_pair = attn @ e  (the big HBM read) ----
    {
        const float4* ebase = (const float4*)(e + (size_t)bi * Ll * Dd);
        float acc[NH][4];
        #pragma unroll
        for (int n = 0; n < NH; n++) { acc[n][0]=0.f; acc[n][1]=0.f; acc[n][2]=0.f; acc[n][3]=0.f; }
        int j0 = warp * 48;
        #pragma unroll 2
        for (int j = j0; j < j0 + 48; j++) {
            float4 ev = ebase[j * 32 + lane];
            float4 a0 = *(const float4*)&attn_t[j * NH];
            float4 a1 = *(const float4*)&attn_t[j * NH + 4];
            float an[NH] = {a0.x, a0.y, a0.z, a0.w, a1.x, a1.y, a1.z, a1.w};
            #pragma unroll
            for (int n = 0; n < NH; n++) {
                acc[n][0] += an[n] * ev.x;
                acc[n][1] += an[n] * ev.y;
                acc[n][2] += an[n] * ev.z;
                acc[n][3] += an[n] * ev.w;
            }
        }
        __syncthreads();   // attn-row region free now; reuse smem_u for reduction
        #pragma unroll
        for (int stride = 4; stride >= 1; stride >>= 1) {
            if (warp >= stride && warp < 2 * stride) {
                float* dstb = &smem_u[(warp - stride) * 1024];
                #pragma unroll
                for (int n = 0; n < NH; n++)
                    *(float4*)&dstb[n * 128 + lane * 4] =
                        make_float4(acc[n][0], acc[n][1], acc[n][2], acc[n][3]);
            }
            __syncthreads();
            if (warp < stride) {
                const float* srcb = &smem_u[warp * 1024];
                #pragma unroll
                for (int n = 0; n < NH; n++) {
                    float4 v = *(const float4*)&srcb[n * 128 + lane * 4];
                    acc[n][0] += v.x; acc[n][1] += v.y; acc[n][2] += v.z; acc[n][3] += v.w;
                }
            }
            __syncthreads();
        }
        if (warp == 0) {
            #pragma unroll
            for (int n = 0; n < NH; n++)
                *(float4*)&feat[128 + n * 128 + lane * 4] =
                    make_float4(acc[n][0], acc[n][1], acc[n][2], acc[n][3]); // out_pair: 128+n*128+d
        }
    }
}

// ---------------- kernel 4: out = feat @ Wo + bo ----------------
#define TMR 8
#define KC 64
__global__ __launch_bounds__(256) void out_kernel(
    const float* __restrict__ Wo, const float* __restrict__ bo, float* __restrict__ out)
{
    int row0 = blockIdx.x * TMR;
    int tid = threadIdx.x;
    int tx = tid & 31;     // cols tx*4 .. tx*4+3
    int ty = tid >> 5;     // row within tile
    __shared__ __align__(16) float As[TMR * KC];
    __shared__ __align__(16) float Bs[KC * Dd];
    float acc0 = 0.f, acc1 = 0.f, acc2 = 0.f, acc3 = 0.f;
    for (int k0 = 0; k0 < FEAT; k0 += KC) {
        for (int m = tid; m < TMR * KC; m += 256) {
            int rr = m >> 6, kk = m & (KC - 1);
            As[m] = g_feat[(row0 + rr) * FEAT + k0 + kk];
        }
        {
            const float4* wsrc = (const float4*)(Wo + (size_t)k0 * Dd);
            float4* bdst = (float4*)Bs;
            for (int m = tid; m < KC * Dd / 4; m += 256) bdst[m] = wsrc[m];
        }
        __syncthreads();
        #pragma unroll 4
        for (int kk = 0; kk < KC; kk++) {
            float av = As[ty * KC + kk];
            float4 bv = *(const float4*)&Bs[kk * Dd + tx * 4];
            acc0 += av * bv.x; acc1 += av * bv.y; acc2 += av * bv.z; acc3 += av * bv.w;
        }
        __syncthreads();
    }
    float4 bb = *(const float4*)&bo[tx * 4];
    int row = row0 + ty;
    *(float4*)&out[(size_t)row * Dd + tx * 4] =
        make_float4(acc0 + bb.x, acc1 + bb.y, acc2 + bb.z, acc3 + bb.w);
}

// ---------------- launch ----------------
extern "C" void kernel_launch(void* const* d_in, const int* in_sizes, int n_in,
                              void* d_out, int out_size) {
    const float* x     = (const float*)d_in[0];
    const float* e     = (const float*)d_in[1];
    const float* r     = (const float*)d_in[2];
    const float* t     = (const float*)d_in[3];
    const float* Wqs   = (const float*)d_in[4];
    const float* Wks   = (const float*)d_in[5];
    const float* Wvs   = (const float*)d_in[6];
    const float* Wb    = (const float*)d_in[7];
    const float* Wqp   = (const float*)d_in[8];
    const float* Wkp   = (const float*)d_in[9];
    const float* Wvp   = (const float*)d_in[10];
    const float* gamma = (const float*)d_in[11];
    const float* Wo    = (const float*)d_in[12];
    const float* bo    = (const float*)d_in[13];
    float* out = (float*)d_out;

    proj_kernel<<<Bb * Ll, 128>>>(x, r, t, Wqs, Wks, Wvs, Wqp, Wkp, Wvp);
    bias_kernel<<<Bb * Ll, 256>>>(e, Wb);
    attn_kernel<<<Bb * Ll, 256>>>(e, r, t, gamma);
    out_kernel<<<(Bb * Ll) / TMR, 256>>>(Wo, bo, out);
}

// round 5
// speedup vs baseline: 1.3748x; 1.3675x over previous
#include <cuda_runtime.h>
#include <math.h>

#define Bb 2
#define Ll 384
#define Dd 128
#define NH 8
#define DHSc 16
#define NPC 12            // DHP*3
#define FEAT 1280
#define KSPLIT 5
#define OUTROWS (Bb*Ll)

// ---------------- scratch (no allocations allowed) ----------------
static __device__ __align__(16) float g_qs[Bb*NH*Ll*DHSc];
static __device__ __align__(16) float g_ks[Bb*NH*Ll*DHSc];
static __device__ __align__(16) float g_vs[Bb*NH*Ll*DHSc];
static __device__ __align__(16) float g_qp[Bb*NH*Ll*NPC];
static __device__ __align__(16) float g_kp[Bb*NH*Ll*NPC];
static __device__ __align__(16) float g_vp[Bb*NH*Ll*NPC];
static __device__ __align__(16) float g_qq[Bb*NH*Ll];
static __device__ __align__(16) float g_kk[Bb*NH*Ll];
static __device__ __align__(16) float g_feat[Bb*Ll*FEAT];
static __device__ __align__(16) float g_part[KSPLIT*OUTROWS*Dd];

// ---------------- kernel 1: projections ----------------
__global__ __launch_bounds__(128) void proj_kernel(
    const float* __restrict__ x, const float* __restrict__ r, const float* __restrict__ t,
    const float* __restrict__ Wqs, const float* __restrict__ Wks, const float* __restrict__ Wvs,
    const float* __restrict__ Wqp, const float* __restrict__ Wkp, const float* __restrict__ Wvp)
{
    int bi = blockIdx.x;
    int b = bi / Ll, i = bi % Ll;
    int tid = threadIdx.x;
    __shared__ float xs[Dd];
    __shared__ float rs[9], ts[3];
    __shared__ float xp[96];
    __shared__ float sq[96];
    xs[tid] = x[bi * Dd + tid];
    if (tid < 9) rs[tid] = r[bi * 9 + tid];
    else if (tid >= 16 && tid < 19) ts[tid - 16] = t[bi * 3 + (tid - 16)];
    __syncthreads();
    {
        float a0 = 0.f, a1 = 0.f, a2 = 0.f;
        #pragma unroll 4
        for (int k = 0; k < Dd; k++) {
            float xv = xs[k];
            a0 += xv * Wqs[k * Dd + tid];
            a1 += xv * Wks[k * Dd + tid];
            a2 += xv * Wvs[k * Dd + tid];
        }
        int n = tid >> 4, d = tid & 15;
        int o = ((b * NH + n) * Ll + i) * DHSc + d;
        g_qs[o] = a0; g_ks[o] = a1; g_vs[o] = a2;
    }
    #pragma unroll
    for (int w = 0; w < 3; w++) {
        const float* W = (w == 0) ? Wqp : (w == 1) ? Wkp : Wvp;
        float* dst = (w == 0) ? g_qp : (w == 1) ? g_kp : g_vp;
        if (tid < 96) {
            float a = 0.f;
            #pragma unroll 4
            for (int k = 0; k < Dd; k++) a += xs[k] * W[k * 96 + tid];
            xp[tid] = a;
        }
        __syncthreads();
        if (tid < 96) {
            int n = tid / 12, pc = tid % 12, p = pc / 3, c = pc % 3;
            const float* xb = &xp[n * 12 + p * 3];
            float v = xb[0] * rs[c] + xb[1] * rs[3 + c] + xb[2] * rs[6 + c] + ts[c];
            dst[((b * NH + n) * Ll + i) * NPC + pc] = v;
            sq[tid] = v * v;
        }
        __syncthreads();
        if (w < 2 && tid < NH) {
            float s = 0.f;
            #pragma unroll
            for (int m = 0; m < 12; m++) s += sq[tid * 12 + m];
            (w == 0 ? g_qq : g_kk)[(b * NH + tid) * Ll + i] = s;
        }
        __syncthreads();
    }
}

// warp reduce: 32 lanes each hold acc[0..7]; returns (in ret) lane l = total sum of acc[l&7]
__device__ __forceinline__ float warp_reduce8(float acc[NH], int lane) {
    #pragma unroll
    for (int n = 0; n < NH; n++) {
        acc[n] += __shfl_xor_sync(0xffffffffu, acc[n], 16);
        acc[n] += __shfl_xor_sync(0xffffffffu, acc[n], 8);
    }
    float r4[4];
    #pragma unroll
    for (int m = 0; m < 4; m++) {
        float send = (lane & 4) ? acc[m] : acc[m + 4];
        float keep = (lane & 4) ? acc[m + 4] : acc[m];
        r4[m] = keep + __shfl_xor_sync(0xffffffffu, send, 4);
    }
    float r2[2];
    #pragma unroll
    for (int m = 0; m < 2; m++) {
        float send = (lane & 2) ? r4[m] : r4[m + 2];
        float keep = (lane & 2) ? r4[m + 2] : r4[m];
        r2[m] = keep + __shfl_xor_sync(0xffffffffu, send, 2);
    }
    float send = (lane & 1) ? r2[0] : r2[1];
    float keep = (lane & 1) ? r2[1] : r2[0];
    return keep + __shfl_xor_sync(0xffffffffu, send, 1);
}

// ---------------- kernel 2: fused bias + logits + softmax + all attention outputs ----------------
__global__ __launch_bounds__(256) void attn_kernel(
    const float* __restrict__ e, const float* __restrict__ Wb,
    const float* __restrict__ r, const float* __restrict__ t,
    const float* __restrict__ gamma)
{
    int bi = blockIdx.x;
    int b = bi / Ll, i = bi % Ll;
    int tid = threadIdx.x;
    int warp = tid >> 5, lane = tid & 31;

    __shared__ __align__(16) float smem_u[4096];    // bias/logit/attn rows (3072), then out_pair tree (4096)
    __shared__ __align__(16) float attn_t[Ll * NH]; // attn transposed: [j][n]
    __shared__ float sqs[NH * DHSc];
    __shared__ float sqp[NH * NPC];
    __shared__ float sqq[NH], gam[NH];
    __shared__ float rs[9], ts[3];
    __shared__ float op_s[96], opl2[96];
    __shared__ float ps[256], pp[192];

    float* attn = smem_u;

    if (tid < 128) {
        int n = tid >> 4, d = tid & 15;
        sqs[tid] = g_qs[((b * NH + n) * Ll + i) * DHSc + d];
    } else if (tid < 224) {
        int m = tid - 128, n = m / 12, pc = m % 12;
        sqp[m] = g_qp[((b * NH + n) * Ll + i) * NPC + pc];
    } else if (tid < 232) {
        int n = tid - 224;
        sqq[n] = g_qq[(b * NH + n) * Ll + i];
        gam[n] = gamma[n];
    } else if (tid < 241) {
        rs[tid - 232] = r[bi * 9 + (tid - 232)];
    } else if (tid < 244) {
        ts[tid - 241] = t[bi * 3 + (tid - 241)];
    }

    // ---- phase 1: bias = e_row @ Wb, streamed from HBM (first and only HBM pass over e row) ----
    {
        float wreg[4][NH];
        #pragma unroll
        for (int q = 0; q < 4; q++)
            #pragma unroll
            for (int n = 0; n < NH; n++)
                wreg[q][n] = Wb[(lane * 4 + q) * NH + n];
        const float4* erow = (const float4*)(e + (size_t)bi * Ll * Dd);
        for (int j = warp; j < Ll; j += 16) {
            float4 va = erow[j * 32 + lane];
            float4 vb = erow[(j + 8) * 32 + lane];
            float accA[NH], accB[NH];
            #pragma unroll
            for (int n = 0; n < NH; n++) {
                accA[n] = va.x * wreg[0][n] + va.y * wreg[1][n] + va.z * wreg[2][n] + va.w * wreg[3][n];
                accB[n] = vb.x * wreg[0][n] + vb.y * wreg[1][n] + vb.z * wreg[2][n] + vb.w * wreg[3][n];
            }
            float ra = warp_reduce8(accA, lane);
            float rb = warp_reduce8(accB, lane);
            if (lane < 8) {
                attn[lane * Ll + j] = ra;        // bias stored at [n][j]
                attn[lane * Ll + j + 8] = rb;
            }
        }
    }
    __syncthreads();

    // ---- phase 2: logits (reads bias in place, overwrites with logit) ----
    for (int m = tid; m < NH * Ll; m += 256) {
        int n = m / Ll, j = m - n * Ll;
        const float4* kr = (const float4*)&g_ks[((b * NH + n) * Ll + j) * DHSc];
        float4 k0 = kr[0], k1 = kr[1], k2 = kr[2], k3 = kr[3];
        const float* q = &sqs[n * DHSc];
        float s = q[0]*k0.x + q[1]*k0.y + q[2]*k0.z + q[3]*k0.w
                + q[4]*k1.x + q[5]*k1.y + q[6]*k1.z + q[7]*k1.w
                + q[8]*k2.x + q[9]*k2.y + q[10]*k2.z + q[11]*k2.w
                + q[12]*k3.x + q[13]*k3.y + q[14]*k3.z + q[15]*k3.w;
        const float* kp = &g_kp[((b * NH + n) * Ll + j) * NPC];
        const float* qp = &sqp[n * NPC];
        float cr = 0.f;
        #pragma unroll
        for (int u = 0; u < NPC; u++) cr += qp[u] * kp[u];
        float d2 = sqq[n] + g_kk[(b * NH + n) * Ll + j] - 2.f * cr;
        float lg = 0.5773502691896258f *
            (0.25f * s + attn[m] - 0.125f * gam[n] * d2);
        attn[m] = lg;
    }
    __syncthreads();

    // ---- phase 3: softmax, warp w handles head w ----
    {
        float* row = &attn[warp * Ll];
        float mx = -1e30f;
        for (int j = lane; j < Ll; j += 32) mx = fmaxf(mx, row[j]);
        #pragma unroll
        for (int off = 16; off > 0; off >>= 1)
            mx = fmaxf(mx, __shfl_xor_sync(0xffffffffu, mx, off));
        float sum = 0.f;
        for (int j = lane; j < Ll; j += 32) {
            float ex = __expf(row[j] - mx);
            row[j] = ex;
            sum += ex;
        }
        #pragma unroll
        for (int off = 16; off > 0; off >>= 1)
            sum += __shfl_xor_sync(0xffffffffu, sum, off);
        float inv = 1.f / sum;
        for (int j = lane; j < Ll; j += 32) {
            float a = row[j] * inv;
            row[j] = a;
            attn_t[j * NH + warp] = a;
        }
    }
    __syncthreads();

    float* feat = &g_feat[bi * FEAT];

    // ---- phase 4: out_scalar (attn @ vs) and op (attn @ vp), split over j-halves ----
    {
        // scalar: 256 tasks = 128 (n,d) x 2 j-halves
        {
            int jh = tid >> 7, dt = tid & 127;
            int n = dt >> 4, d = dt & 15;
            const float* row = &attn[n * Ll];
            const float* vb = &g_vs[((b * NH + n) * Ll) * DHSc + d];
            float a = 0.f;
            int j0 = jh * 192;
            #pragma unroll 8
            for (int j = j0; j < j0 + 192; j++) a += row[j] * vb[j * DHSc];
            ps[tid] = a;
        }
        // point: 192 tasks = 96 (n,pc) x 2 j-halves
        if (tid < 192) {
            int jh = tid / 96, m = tid - jh * 96;
            int n = m / 12, pc = m % 12;
            const float* row = &attn[n * Ll];
            const float* vb = &g_vp[((b * NH + n) * Ll) * NPC + pc];
            float a = 0.f;
            int j0 = jh * 192;
            #pragma unroll 8
            for (int j = j0; j < j0 + 192; j++) a += row[j] * vb[j * NPC];
            pp[tid] = a;
        }
    }
    __syncthreads();
    if (tid < 128) feat[tid] = ps[tid] + ps[128 + tid];          // out_scalar
    else if (tid < 224) { int m = tid - 128; op_s[m] = pp[m] + pp[96 + m]; }
    __syncthreads();

    // ---- phase 5: op_local (inverse rotation) + norm ----
    if (tid < 96) {
        int pc = tid % 12, nb = tid - pc;
        int p3 = (pc / 3) * 3, c = pc % 3;
        const float* ob = &op_s[nb + p3];
        float v = (ob[0] - ts[0]) * rs[c * 3 + 0]
                + (ob[1] - ts[1]) * rs[c * 3 + 1]
                + (ob[2] - ts[2]) * rs[c * 3 + 2];
        feat[1152 + tid] = v;
        opl2[tid] = v * v;
    }
    __syncthreads();
    if (tid < 32) {
        int base = (tid >> 2) * 12 + (tid & 3) * 3;
        feat[1248 + tid] = sqrtf(opl2[base] + opl2[base + 1] + opl2[base + 2]);
    }

    // ---- phase 6: out_pair = attn @ e (second pass, mostly L2-resident) ----
    {
        const float4* ebase = (const float4*)(e + (size_t)bi * Ll * Dd);
        float acc[NH][4];
        #pragma unroll
        for (int n = 0; n < NH; n++) { acc[n][0]=0.f; acc[n][1]=0.f; acc[n][2]=0.f; acc[n][3]=0.f; }
        int j0 = warp * 48;
        #pragma unroll 2
        for (int j = j0; j < j0 + 48; j++) {
            float4 ev = ebase[j * 32 + lane];
            float4 a0 = *(const float4*)&attn_t[j * NH];
            float4 a1 = *(const float4*)&attn_t[j * NH + 4];
            float an[NH] = {a0.x, a0.y, a0.z, a0.w, a1.x, a1.y, a1.z, a1.w};
            #pragma unroll
            for (int n = 0; n < NH; n++) {
                acc[n][0] += an[n] * ev.x;
                acc[n][1] += an[n] * ev.y;
                acc[n][2] += an[n] * ev.z;
                acc[n][3] += an[n] * ev.w;
            }
        }
        __syncthreads();   // attn region no longer needed; reuse smem_u for tree reduction
        #pragma unroll
        for (int stride = 4; stride >= 1; stride >>= 1) {
            if (warp >= stride && warp < 2 * stride) {
                float* dstb = &smem_u[(warp - stride) * 1024];
                #pragma unroll
                for (int n = 0; n < NH; n++)
                    *(float4*)&dstb[n * 128 + lane * 4] =
                        make_float4(acc[n][0], acc[n][1], acc[n][2], acc[n][3]);
            }
            __syncthreads();
            if (warp < stride) {
                const float* srcb = &smem_u[warp * 1024];
                #pragma unroll
                for (int n = 0; n < NH; n++) {
                    float4 v = *(const float4*)&srcb[n * 128 + lane * 4];
                    acc[n][0] += v.x; acc[n][1] += v.y; acc[n][2] += v.z; acc[n][3] += v.w;
                }
            }
            __syncthreads();
        }
        if (warp == 0) {
            #pragma unroll
            for (int n = 0; n < NH; n++)
                *(float4*)&feat[128 + n * 128 + lane * 4] =
                    make_float4(acc[n][0], acc[n][1], acc[n][2], acc[n][3]);
        }
    }
}

// ---------------- kernel 3a: partial out GEMM (k-split) ----------------
#define TMR 8
#define KC 64
__global__ __launch_bounds__(256) void out_part_kernel(const float* __restrict__ Wo)
{
    int row0 = blockIdx.x * TMR;
    int kbase = blockIdx.y * (FEAT / KSPLIT);
    int tid = threadIdx.x;
    int tx = tid & 31;     // cols tx*4 .. tx*4+3
    int ty = tid >> 5;     // row within tile
    __shared__ __align__(16) float As[TMR * KC];
    __shared__ __align__(16) float Bs[KC * Dd];
    float acc0 = 0.f, acc1 = 0.f, acc2 = 0.f, acc3 = 0.f;
    #pragma unroll
    for (int tile = 0; tile < (FEAT / KSPLIT) / KC; tile++) {
        int k0 = kbase + tile * KC;
        for (int m = tid; m < TMR * KC; m += 256) {
            int rr = m >> 6, kk = m & (KC - 1);
            As[m] = g_feat[(row0 + rr) * FEAT + k0 + kk];
        }
        {
            const float4* wsrc = (const float4*)(Wo + (size_t)k0 * Dd);
            float4* bdst = (float4*)Bs;
            for (int m = tid; m < KC * Dd / 4; m += 256) bdst[m] = wsrc[m];
        }
        __syncthreads();
        #pragma unroll 4
        for (int kk = 0; kk < KC; kk++) {
            float av = As[ty * KC + kk];
            float4 bv = *(const float4*)&Bs[kk * Dd + tx * 4];
            acc0 += av * bv.x; acc1 += av * bv.y; acc2 += av * bv.z; acc3 += av * bv.w;
        }
        __syncthreads();
    }
    int row = row0 + ty;
    *(float4*)&g_part[((size_t)blockIdx.y * OUTROWS + row) * Dd + tx * 4] =
        make_float4(acc0, acc1, acc2, acc3);
}

// ---------------- kernel 3b: reduce partials + bias ----------------
__global__ __launch_bounds__(256) void out_reduce_kernel(
    const float* __restrict__ bo, float* __restrict__ out)
{
    int idx = blockIdx.x * 256 + threadIdx.x;   // 0 .. 98303
    int c = idx & (Dd - 1);
    float a = bo[c];
    #pragma unroll
    for (int s = 0; s < KSPLIT; s++) a += g_part[s * (OUTROWS * Dd) + idx];
    out[idx] = a;
}

// ---------------- launch ----------------
extern "C" void kernel_launch(void* const* d_in, const int* in_sizes, int n_in,
                              void* d_out, int out_size) {
    const float* x     = (const float*)d_in[0];
    const float* e     = (const float*)d_in[1];
    const float* r     = (const float*)d_in[2];
    const float* t     = (const float*)d_in[3];
    const float* Wqs   = (const float*)d_in[4];
    const float* Wks   = (const float*)d_in[5];
    const float* Wvs   = (const float*)d_in[6];
    const float* Wb    = (const float*)d_in[7];
    const float* Wqp   = (const float*)d_in[8];
    const float* Wkp   = (const float*)d_in[9];
    const float* Wvp   = (const float*)d_in[10];
    const float* gamma = (const float*)d_in[11];
    const float* Wo    = (const float*)d_in[12];
    const float* bo    = (const float*)d_in[13];
    float* out = (float*)d_out;

    proj_kernel<<<Bb * Ll, 128>>>(x, r, t, Wqs, Wks, Wvs, Wqp, Wkp, Wvp);
    attn_kernel<<<Bb * Ll, 256>>>(e, Wb, r, t, gamma);
    out_part_kernel<<<dim3((Bb * Ll) / TMR, KSPLIT), 256>>>(Wo);
    out_reduce_kernel<<<(OUTROWS * Dd) / 256, 256>>>(bo, out);
}